// round 1
// baseline (speedup 1.0000x reference)
#include <cuda_runtime.h>
#include <cuda_fp16.h>
#include <stdint.h>

// Problem constants
#define HB 4
#define HN 2048
#define HC 1024
#define HH 16
#define HD 64
#define MROWS (HB*HN)        // 8192
#define QKVC  (3*HC)         // 3072

// ---------------- scratch (device globals; no runtime alloc) ----------------
__device__ __align__(256) __half g_Xhi[MROWS*HC];
__device__ __align__(256) __half g_Xlo[MROWS*HC];
__device__ __align__(256) __half g_Wqkvhi[QKVC*HC];
__device__ __align__(256) __half g_Wqkvlo[QKVC*HC];
__device__ __align__(256) __half g_Wouthi[HC*HC];
__device__ __align__(256) __half g_Woutlo[HC*HC];
__device__ __align__(256) __half g_QKV[(size_t)MROWS*QKVC];
__device__ __align__(256) __half g_Ohi[MROWS*HC];
__device__ __align__(256) __half g_Olo[MROWS*HC];

// ---------------- PTX helpers ----------------
__device__ __forceinline__ void ldm_x4(uint32_t* r, const __half* p) {
    uint32_t addr = (uint32_t)__cvta_generic_to_shared(p);
    asm volatile("ldmatrix.sync.aligned.m8n8.x4.shared.b16 {%0,%1,%2,%3}, [%4];\n"
        : "=r"(r[0]), "=r"(r[1]), "=r"(r[2]), "=r"(r[3]) : "r"(addr));
}
__device__ __forceinline__ void ldm_x4_t(uint32_t* r, const __half* p) {
    uint32_t addr = (uint32_t)__cvta_generic_to_shared(p);
    asm volatile("ldmatrix.sync.aligned.m8n8.x4.trans.shared.b16 {%0,%1,%2,%3}, [%4];\n"
        : "=r"(r[0]), "=r"(r[1]), "=r"(r[2]), "=r"(r[3]) : "r"(addr));
}
__device__ __forceinline__ void mma_f16(float* c, const uint32_t* a, const uint32_t* b) {
    asm volatile(
        "mma.sync.aligned.m16n8k16.row.col.f32.f16.f16.f32 "
        "{%0,%1,%2,%3}, {%4,%5,%6,%7}, {%8,%9}, {%0,%1,%2,%3};\n"
        : "+f"(c[0]), "+f"(c[1]), "+f"(c[2]), "+f"(c[3])
        : "r"(a[0]), "r"(a[1]), "r"(a[2]), "r"(a[3]), "r"(b[0]), "r"(b[1]));
}
__device__ __forceinline__ uint32_t h2_as_u32(__half2 v) {
    return *reinterpret_cast<uint32_t*>(&v);
}

// ---------------- split conversion fp32 -> (hi, lo) fp16 ----------------
__global__ void split_convert_kernel(const float* __restrict__ src,
                                     __half* __restrict__ hi,
                                     __half* __restrict__ lo, int n) {
    int i = blockIdx.x * blockDim.x + threadIdx.x;
    if (i < n) {
        float v = src[i];
        __half h = __float2half_rn(v);
        hi[i] = h;
        lo[i] = __float2half_rn(v - __half2float(h));
    }
}

// ---------------- split-fp16 GEMM: C[M,N] = A[M,K] @ B[N,K]^T ----------------
// 3 passes: Ahi*Bhi + Ahi*Blo + Alo*Bhi accumulated in fp32.
// EPI==0: write fp16 to outH (ld = ldo).  EPI==1: write fp32 + bias to outF.
#define BM 128
#define BN 128
#define BK 32
#define APAD 40   // smem row stride in halfs (80B: 16B aligned, conflict-free)

template<int EPI>
__global__ __launch_bounds__(256)
void gemm_split_kernel(const __half* __restrict__ Ahi, const __half* __restrict__ Alo,
                       const __half* __restrict__ Bhi, const __half* __restrict__ Blo,
                       int K,
                       __half* __restrict__ outH, int ldo,
                       float* __restrict__ outF, const float* __restrict__ bias) {
    __shared__ __align__(16) __half As[BM * APAD];
    __shared__ __align__(16) __half Bs[BN * APAD];

    const int tid  = threadIdx.x;
    const int lane = tid & 31;
    const int warp = tid >> 5;
    const int wm = warp & 3;   // 4 warps along M
    const int wn = warp >> 2;  // 2 warps along N
    const int bm0 = blockIdx.y * BM;
    const int bn0 = blockIdx.x * BN;

    float acc[2][8][4];
#pragma unroll
    for (int mi = 0; mi < 2; ++mi)
#pragma unroll
        for (int n = 0; n < 8; ++n)
#pragma unroll
            for (int k = 0; k < 4; ++k) acc[mi][n][k] = 0.f;

    const int lr = tid >> 2;          // 0..63
    const int lc = (tid & 3) * 8;     // 0,8,16,24

    // ldmatrix coordinate bases (within block tile)
    const int a_row = wm * 32 + (lane & 7) + ((lane >> 3) & 1) * 8;   // + mi*16
    const int a_col = (lane >> 4) * 8;                                // + kc*16
    const int b_row = wn * 64 + (lane >> 4) * 8 + (lane & 7);         // + np*16
    const int b_col = ((lane >> 3) & 1) * 8;                          // + kc*16

#pragma unroll 1
    for (int pass = 0; pass < 3; ++pass) {
        const __half* A = (pass == 2) ? Alo : Ahi;
        const __half* Bp = (pass == 1) ? Blo : Bhi;
#pragma unroll 1
        for (int k0 = 0; k0 < K; k0 += BK) {
            __syncthreads();
            *(uint4*)&As[lr * APAD + lc] =
                *(const uint4*)&A[(size_t)(bm0 + lr) * K + k0 + lc];
            *(uint4*)&As[(lr + 64) * APAD + lc] =
                *(const uint4*)&A[(size_t)(bm0 + lr + 64) * K + k0 + lc];
            *(uint4*)&Bs[lr * APAD + lc] =
                *(const uint4*)&Bp[(size_t)(bn0 + lr) * K + k0 + lc];
            *(uint4*)&Bs[(lr + 64) * APAD + lc] =
                *(const uint4*)&Bp[(size_t)(bn0 + lr + 64) * K + k0 + lc];
            __syncthreads();
#pragma unroll
            for (int kc = 0; kc < 2; ++kc) {
                uint32_t afr[2][4];
#pragma unroll
                for (int mi = 0; mi < 2; ++mi)
                    ldm_x4(afr[mi], &As[(a_row + mi * 16) * APAD + a_col + kc * 16]);
                uint32_t bfr[8][2];
#pragma unroll
                for (int np = 0; np < 4; ++np) {
                    uint32_t r[4];
                    ldm_x4(r, &Bs[(b_row + np * 16) * APAD + b_col + kc * 16]);
                    bfr[2 * np][0] = r[0]; bfr[2 * np][1] = r[1];
                    bfr[2 * np + 1][0] = r[2]; bfr[2 * np + 1][1] = r[3];
                }
#pragma unroll
                for (int mi = 0; mi < 2; ++mi)
#pragma unroll
                    for (int n = 0; n < 8; ++n)
                        mma_f16(acc[mi][n], afr[mi], bfr[n]);
            }
        }
    }

    // epilogue
    const int g = lane >> 2, tg = lane & 3;
#pragma unroll
    for (int mi = 0; mi < 2; ++mi) {
        int row0 = bm0 + wm * 32 + mi * 16 + g;
#pragma unroll
        for (int n = 0; n < 8; ++n) {
            int col = bn0 + wn * 64 + n * 8 + 2 * tg;
            if (EPI == 0) {
                __half2 v01 = __floats2half2_rn(acc[mi][n][0], acc[mi][n][1]);
                __half2 v23 = __floats2half2_rn(acc[mi][n][2], acc[mi][n][3]);
                *(__half2*)&outH[(size_t)row0 * ldo + col] = v01;
                *(__half2*)&outH[(size_t)(row0 + 8) * ldo + col] = v23;
            } else {
                float b0 = bias[col], b1 = bias[col + 1];
                float2 v01 = make_float2(acc[mi][n][0] + b0, acc[mi][n][1] + b1);
                float2 v23 = make_float2(acc[mi][n][2] + b0, acc[mi][n][3] + b1);
                *(float2*)&outF[(size_t)row0 * ldo + col] = v01;
                *(float2*)&outF[(size_t)(row0 + 8) * ldo + col] = v23;
            }
        }
    }
}

// ---------------- flash attention ----------------
// Grid: (N/64, B*H). Block: 128 threads (4 warps), each warp owns 16 q-rows.
// Q,K,V read from g_QKV [8192 x 3072] at offsets 0 / 1024 / 2048 (+h*64).
#define FPAD 72   // smem row stride in halfs (144B)

__global__ __launch_bounds__(128)
void flash_kernel() {
    __shared__ __align__(16) __half bufA[64 * FPAD];  // Q, then K tiles
    __shared__ __align__(16) __half bufV[64 * FPAD];  // V tiles

    const int tid  = threadIdx.x;
    const int lane = tid & 31;
    const int warp = tid >> 5;
    const int qt = blockIdx.x;
    const int bh = blockIdx.y;
    const int b = bh >> 4, h = bh & 15;

    const size_t base = (size_t)b * HN * QKVC + (size_t)h * HD;

    // stage Q tile (64 x 64)
#pragma unroll
    for (int i = 0; i < 4; ++i) {
        int idx = tid + i * 128;
        int r = idx >> 3, c = (idx & 7) * 8;
        *(uint4*)&bufA[r * FPAD + c] =
            *(const uint4*)&g_QKV[base + (size_t)(qt * 64 + r) * QKVC + c];
    }
    __syncthreads();

    // Q fragments: 16 rows x 64 d per warp => 4 k16 chunks
    uint32_t qa[4][4];
    const int a_row = warp * 16 + (lane & 7) + ((lane >> 3) & 1) * 8;
    const int a_col = (lane >> 4) * 8;
#pragma unroll
    for (int kc = 0; kc < 4; ++kc)
        ldm_x4(qa[kc], &bufA[a_row * FPAD + a_col + kc * 16]);
    __syncthreads();

    float o[8][4];
#pragma unroll
    for (int n = 0; n < 8; ++n)
#pragma unroll
        for (int k = 0; k < 4; ++k) o[n][k] = 0.f;
    float m0 = -1e30f, m1 = -1e30f, l0 = 0.f, l1 = 0.f;

    const int kb_row = (lane >> 4) * 8 + (lane & 7);   // + np*16
    const int kb_col = ((lane >> 3) & 1) * 8;          // + kc*16
    const int v_row  = ((lane >> 3) & 1) * 8 + (lane & 7);  // + jc*16
    const int v_col  = (lane >> 4) * 8;                     // + dp*16

#pragma unroll 1
    for (int kt = 0; kt < 32; ++kt) {
        const size_t rowbase = base + (size_t)(kt * 64) * QKVC;
#pragma unroll
        for (int i = 0; i < 4; ++i) {
            int idx = tid + i * 128;
            int r = idx >> 3, c = (idx & 7) * 8;
            size_t off = rowbase + (size_t)r * QKVC + c;
            *(uint4*)&bufA[r * FPAD + c] = *(const uint4*)&g_QKV[off + 1024];
            *(uint4*)&bufV[r * FPAD + c] = *(const uint4*)&g_QKV[off + 2048];
        }
        __syncthreads();

        // S = Q @ K^T  (16 x 64 per warp)
        float s[8][4];
#pragma unroll
        for (int n = 0; n < 8; ++n)
#pragma unroll
            for (int k = 0; k < 4; ++k) s[n][k] = 0.f;
#pragma unroll
        for (int kc = 0; kc < 4; ++kc) {
            uint32_t bfr[8][2];
#pragma unroll
            for (int np = 0; np < 4; ++np) {
                uint32_t r[4];
                ldm_x4(r, &bufA[(kb_row + np * 16) * FPAD + kb_col + kc * 16]);
                bfr[2 * np][0] = r[0]; bfr[2 * np][1] = r[1];
                bfr[2 * np + 1][0] = r[2]; bfr[2 * np + 1][1] = r[3];
            }
#pragma unroll
            for (int n = 0; n < 8; ++n)
                mma_f16(s[n], qa[kc], bfr[n]);
        }
        // scale
#pragma unroll
        for (int n = 0; n < 8; ++n)
#pragma unroll
            for (int k = 0; k < 4; ++k) s[n][k] *= 0.125f;

        // online softmax (rows g and g+8 per thread; reduce over lane%4 group)
        float tm0 = -1e30f, tm1 = -1e30f;
#pragma unroll
        for (int n = 0; n < 8; ++n) {
            tm0 = fmaxf(tm0, fmaxf(s[n][0], s[n][1]));
            tm1 = fmaxf(tm1, fmaxf(s[n][2], s[n][3]));
        }
        tm0 = fmaxf(tm0, __shfl_xor_sync(0xffffffffu, tm0, 1));
        tm0 = fmaxf(tm0, __shfl_xor_sync(0xffffffffu, tm0, 2));
        tm1 = fmaxf(tm1, __shfl_xor_sync(0xffffffffu, tm1, 1));
        tm1 = fmaxf(tm1, __shfl_xor_sync(0xffffffffu, tm1, 2));
        float nm0 = fmaxf(m0, tm0), nm1 = fmaxf(m1, tm1);
        float c0 = __expf(m0 - nm0), c1 = __expf(m1 - nm1);
        m0 = nm0; m1 = nm1;

        float rs0 = 0.f, rs1 = 0.f;
#pragma unroll
        for (int n = 0; n < 8; ++n) {
            s[n][0] = __expf(s[n][0] - m0); rs0 += s[n][0];
            s[n][1] = __expf(s[n][1] - m0); rs0 += s[n][1];
            s[n][2] = __expf(s[n][2] - m1); rs1 += s[n][2];
            s[n][3] = __expf(s[n][3] - m1); rs1 += s[n][3];
        }
        rs0 += __shfl_xor_sync(0xffffffffu, rs0, 1);
        rs0 += __shfl_xor_sync(0xffffffffu, rs0, 2);
        rs1 += __shfl_xor_sync(0xffffffffu, rs1, 1);
        rs1 += __shfl_xor_sync(0xffffffffu, rs1, 2);
        l0 = l0 * c0 + rs0;
        l1 = l1 * c1 + rs1;
#pragma unroll
        for (int n = 0; n < 8; ++n) {
            o[n][0] *= c0; o[n][1] *= c0; o[n][2] *= c1; o[n][3] *= c1;
        }

        // O += P @ V   (P fragments built from s; V via ldmatrix.trans)
#pragma unroll
        for (int jc = 0; jc < 4; ++jc) {
            uint32_t pa[4];
            pa[0] = h2_as_u32(__floats2half2_rn(s[2 * jc][0],     s[2 * jc][1]));
            pa[1] = h2_as_u32(__floats2half2_rn(s[2 * jc][2],     s[2 * jc][3]));
            pa[2] = h2_as_u32(__floats2half2_rn(s[2 * jc + 1][0], s[2 * jc + 1][1]));
            pa[3] = h2_as_u32(__floats2half2_rn(s[2 * jc + 1][2], s[2 * jc + 1][3]));
            uint32_t bv[8][2];
#pragma unroll
            for (int dp = 0; dp < 4; ++dp) {
                uint32_t r[4];
                ldm_x4_t(r, &bufV[(v_row + jc * 16) * FPAD + v_col + dp * 16]);
                bv[2 * dp][0] = r[0]; bv[2 * dp][1] = r[1];
                bv[2 * dp + 1][0] = r[2]; bv[2 * dp + 1][1] = r[3];
            }
#pragma unroll
            for (int dt = 0; dt < 8; ++dt)
                mma_f16(o[dt], pa, bv[dt]);
        }
        __syncthreads();
    }

    // epilogue: divide by l, write O as (hi, lo) fp16
    const float inv0 = 1.0f / l0, inv1 = 1.0f / l1;
    const int g = lane >> 2, tg = lane & 3;
    const int qrow = qt * 64 + warp * 16 + g;
    const size_t obase = ((size_t)b * HN + qrow) * HC + h * HD;
#pragma unroll
    for (int dt = 0; dt < 8; ++dt) {
        int col = dt * 8 + 2 * tg;
        float v0 = o[dt][0] * inv0, v1 = o[dt][1] * inv0;
        float v2 = o[dt][2] * inv1, v3 = o[dt][3] * inv1;
        __half h0 = __float2half_rn(v0), h1 = __float2half_rn(v1);
        __half h2v = __float2half_rn(v2), h3 = __float2half_rn(v3);
        __half e0 = __float2half_rn(v0 - __half2float(h0));
        __half e1 = __float2half_rn(v1 - __half2float(h1));
        __half e2 = __float2half_rn(v2 - __half2float(h2v));
        __half e3 = __float2half_rn(v3 - __half2float(h3));
        *(__half2*)&g_Ohi[obase + col] = __halves2half2(h0, h1);
        *(__half2*)&g_Olo[obase + col] = __halves2half2(e0, e1);
        *(__half2*)&g_Ohi[obase + (size_t)8 * HC + col] = __halves2half2(h2v, h3);
        *(__half2*)&g_Olo[obase + (size_t)8 * HC + col] = __halves2half2(e2, e3);
    }
}

// ---------------- launch ----------------
extern "C" void kernel_launch(void* const* d_in, const int* in_sizes, int n_in,
                              void* d_out, int out_size) {
    const float* x     = (const float*)d_in[0];
    const float* w_qkv = (const float*)d_in[1];
    const float* w_out = (const float*)d_in[2];
    const float* b_out = (const float*)d_in[3];

    __half *xhi, *xlo, *wqh, *wql, *woh, *wol, *qkv, *ohi, *olo;
    cudaGetSymbolAddress((void**)&xhi, g_Xhi);
    cudaGetSymbolAddress((void**)&xlo, g_Xlo);
    cudaGetSymbolAddress((void**)&wqh, g_Wqkvhi);
    cudaGetSymbolAddress((void**)&wql, g_Wqkvlo);
    cudaGetSymbolAddress((void**)&woh, g_Wouthi);
    cudaGetSymbolAddress((void**)&wol, g_Woutlo);
    cudaGetSymbolAddress((void**)&qkv, g_QKV);
    cudaGetSymbolAddress((void**)&ohi, g_Ohi);
    cudaGetSymbolAddress((void**)&olo, g_Olo);

    const int nx = MROWS * HC;        // 8388608
    const int nq = QKVC * HC;         // 3145728
    const int nw = HC * HC;           // 1048576
    split_convert_kernel<<<nx / 256, 256>>>(x, xhi, xlo, nx);
    split_convert_kernel<<<nq / 256, 256>>>(w_qkv, wqh, wql, nq);
    split_convert_kernel<<<nw / 256, 256>>>(w_out, woh, wol, nw);

    // QKV projection: [8192, 3072] fp16
    gemm_split_kernel<0><<<dim3(QKVC / BN, MROWS / BM), 256>>>(
        xhi, xlo, wqh, wql, HC, qkv, QKVC, nullptr, nullptr);

    // attention
    flash_kernel<<<dim3(HN / 64, HB * HH), 128>>>();

    // output projection: fp32 + bias
    gemm_split_kernel<1><<<dim3(HC / BN, MROWS / BM), 256>>>(
        ohi, olo, woh, wol, HC, nullptr, HC, (float*)d_out, b_out);
}

// round 4
// speedup vs baseline: 1.5386x; 1.5386x over previous
#include <cuda_runtime.h>
#include <cuda_fp16.h>
#include <stdint.h>

// Problem constants
#define HB 4
#define HN 2048
#define HC 1024
#define HH 16
#define HD 64
#define MROWS (HB*HN)        // 8192
#define QKVC  (3*HC)         // 3072

// ---------------- scratch (device globals; no runtime alloc) ----------------
__device__ __align__(256) __half g_Xhi[MROWS*HC];
__device__ __align__(256) __half g_Wqkvhi[QKVC*HC];
__device__ __align__(256) __half g_Wqkvlo[QKVC*HC];
__device__ __align__(256) __half g_Wouthi[HC*HC];
__device__ __align__(256) __half g_Woutlo[HC*HC];
__device__ __align__(256) __half g_QKV[(size_t)MROWS*QKVC];
__device__ __align__(256) __half g_O[MROWS*HC];

// ---------------- PTX helpers ----------------
__device__ __forceinline__ void ldm_x4(uint32_t* r, const __half* p) {
    uint32_t addr = (uint32_t)__cvta_generic_to_shared(p);
    asm volatile("ldmatrix.sync.aligned.m8n8.x4.shared.b16 {%0,%1,%2,%3}, [%4];\n"
        : "=r"(r[0]), "=r"(r[1]), "=r"(r[2]), "=r"(r[3]) : "r"(addr));
}
__device__ __forceinline__ void ldm_x4_t(uint32_t* r, const __half* p) {
    uint32_t addr = (uint32_t)__cvta_generic_to_shared(p);
    asm volatile("ldmatrix.sync.aligned.m8n8.x4.trans.shared.b16 {%0,%1,%2,%3}, [%4];\n"
        : "=r"(r[0]), "=r"(r[1]), "=r"(r[2]), "=r"(r[3]) : "r"(addr));
}
__device__ __forceinline__ void mma_f16(float* c, const uint32_t* a, const uint32_t* b) {
    asm volatile(
        "mma.sync.aligned.m16n8k16.row.col.f32.f16.f16.f32 "
        "{%0,%1,%2,%3}, {%4,%5,%6,%7}, {%8,%9}, {%0,%1,%2,%3};\n"
        : "+f"(c[0]), "+f"(c[1]), "+f"(c[2]), "+f"(c[3])
        : "r"(a[0]), "r"(a[1]), "r"(a[2]), "r"(a[3]), "r"(b[0]), "r"(b[1]));
}
__device__ __forceinline__ uint32_t h2_as_u32(__half2 v) {
    return *reinterpret_cast<uint32_t*>(&v);
}
__device__ __forceinline__ void cpasync16(uint32_t dst, const void* src) {
    asm volatile("cp.async.cg.shared.global [%0], [%1], 16;\n" :: "r"(dst), "l"(src) : "memory");
}
__device__ __forceinline__ void cp_commit() {
    asm volatile("cp.async.commit_group;\n" ::: "memory");
}
template<int N>
__device__ __forceinline__ void cp_wait() {
    asm volatile("cp.async.wait_group %0;\n" :: "n"(N) : "memory");
}

// ---------------- conversion kernels ----------------
__global__ void convert_hi_kernel(const float* __restrict__ src,
                                  __half* __restrict__ hi, int n) {
    int i = blockIdx.x * blockDim.x + threadIdx.x;
    int j = 2 * i;
    if (j < n) {
        float2 v = *(const float2*)&src[j];
        *(__half2*)&hi[j] = __floats2half2_rn(v.x, v.y);
    }
}
__global__ void split_convert_kernel(const float* __restrict__ src,
                                     __half* __restrict__ hi,
                                     __half* __restrict__ lo, int n) {
    int i = blockIdx.x * blockDim.x + threadIdx.x;
    int j = 2 * i;
    if (j < n) {
        float2 v = *(const float2*)&src[j];
        __half h0 = __float2half_rn(v.x), h1 = __float2half_rn(v.y);
        *(__half2*)&hi[j] = __halves2half2(h0, h1);
        *(__half2*)&lo[j] = __floats2half2_rn(v.x - __half2float(h0),
                                              v.y - __half2float(h1));
    }
}

// ============================================================================
// Fused 2-combo split GEMM: C = A @ (Bhi + Blo)^T, fp32 accum via mma.sync.
// A [M,K] fp16 (hi only), B [N,K] split. 128x128 tile, BK=32, 2-stage cp.async.
// EPI 0: half out. EPI 1: float out + bias.
// ============================================================================
#define BM 128
#define BN 128
#define BK 32
#define APAD 40                       // halfs: 80B row stride
#define SMT (BM * APAD)               // halfs per tile (5120)
#define GEMM_SMEM (2 * 3 * SMT * 2)   // bytes = 61440

template<int EPI>
__global__ __launch_bounds__(256, 2)
void gemm2_kernel(const __half* __restrict__ A,
                  const __half* __restrict__ Bhi, const __half* __restrict__ Blo,
                  int K,
                  __half* __restrict__ outH, int ldo,
                  float* __restrict__ outF, const float* __restrict__ bias) {
    extern __shared__ __align__(16) __half sm[];

    const int tid  = threadIdx.x;
    const int lane = tid & 31;
    const int warp = tid >> 5;
    const int wm = warp & 3;
    const int wn = warp >> 2;
    const int bm0 = blockIdx.y * BM;
    const int bn0 = blockIdx.x * BN;

    const uint32_t smb = (uint32_t)__cvta_generic_to_shared(sm);

    float acc[2][8][4];
#pragma unroll
    for (int mi = 0; mi < 2; ++mi)
#pragma unroll
        for (int n = 0; n < 8; ++n)
#pragma unroll
            for (int k = 0; k < 4; ++k) acc[mi][n][k] = 0.f;

    // load thread mapping: 512 chunks of 16B per tile, 2 per thread
    const int lr = tid >> 1;          // row 0..127
    const int lc = (tid & 1) * 2;     // chunk col 0 or 2 (each does 2 chunks)

    const int a_row = wm * 32 + (lane & 7) + ((lane >> 3) & 1) * 8;
    const int a_col = (lane >> 4) * 8;
    const int b_row = wn * 64 + (lane >> 4) * 8 + (lane & 7);
    const int b_col = ((lane >> 3) & 1) * 8;

    const int NCH = K / BK;

    auto issue = [&](int ch, int s) {
        const int k0 = ch * BK;
        const uint32_t st = smb + (uint32_t)(s * 3 * SMT) * 2;
        const size_t ga = (size_t)(bm0 + lr) * K + k0 + lc * 8;
        const size_t gb = (size_t)(bn0 + lr) * K + k0 + lc * 8;
        const uint32_t so = (uint32_t)(lr * APAD + lc * 8) * 2;
#pragma unroll
        for (int c = 0; c < 2; ++c) {
            cpasync16(st + so + c * 16, A + ga + c * 8);
            cpasync16(st + (uint32_t)SMT * 2 + so + c * 16, Bhi + gb + c * 8);
            cpasync16(st + (uint32_t)SMT * 4 + so + c * 16, Blo + gb + c * 8);
        }
        cp_commit();
    };

    issue(0, 0);

#pragma unroll 1
    for (int ch = 0; ch < NCH; ++ch) {
        const int s = ch & 1;
        if (ch + 1 < NCH) { issue(ch + 1, s ^ 1); cp_wait<1>(); }
        else              { cp_wait<0>(); }
        __syncthreads();

        const __half* As = sm + s * 3 * SMT;
        const __half* Bh = As + SMT;
        const __half* Bl = Bh + SMT;
#pragma unroll
        for (int kc = 0; kc < 2; ++kc) {
            uint32_t afr[2][4];
#pragma unroll
            for (int mi = 0; mi < 2; ++mi)
                ldm_x4(afr[mi], &As[(a_row + mi * 16) * APAD + a_col + kc * 16]);
            uint32_t bfr[8][2];
#pragma unroll
            for (int np = 0; np < 4; ++np) {
                uint32_t r[4];
                ldm_x4(r, &Bh[(b_row + np * 16) * APAD + b_col + kc * 16]);
                bfr[2 * np][0] = r[0]; bfr[2 * np][1] = r[1];
                bfr[2 * np + 1][0] = r[2]; bfr[2 * np + 1][1] = r[3];
            }
#pragma unroll
            for (int mi = 0; mi < 2; ++mi)
#pragma unroll
                for (int n = 0; n < 8; ++n)
                    mma_f16(acc[mi][n], afr[mi], bfr[n]);
#pragma unroll
            for (int np = 0; np < 4; ++np) {
                uint32_t r[4];
                ldm_x4(r, &Bl[(b_row + np * 16) * APAD + b_col + kc * 16]);
                bfr[2 * np][0] = r[0]; bfr[2 * np][1] = r[1];
                bfr[2 * np + 1][0] = r[2]; bfr[2 * np + 1][1] = r[3];
            }
#pragma unroll
            for (int mi = 0; mi < 2; ++mi)
#pragma unroll
                for (int n = 0; n < 8; ++n)
                    mma_f16(acc[mi][n], afr[mi], bfr[n]);
        }
        __syncthreads();
    }

    // epilogue
    const int g = lane >> 2, tg = lane & 3;
#pragma unroll
    for (int mi = 0; mi < 2; ++mi) {
        int row0 = bm0 + wm * 32 + mi * 16 + g;
#pragma unroll
        for (int n = 0; n < 8; ++n) {
            int col = bn0 + wn * 64 + n * 8 + 2 * tg;
            if (EPI == 0) {
                __half2 v01 = __floats2half2_rn(acc[mi][n][0], acc[mi][n][1]);
                __half2 v23 = __floats2half2_rn(acc[mi][n][2], acc[mi][n][3]);
                *(__half2*)&outH[(size_t)row0 * ldo + col] = v01;
                *(__half2*)&outH[(size_t)(row0 + 8) * ldo + col] = v23;
            } else {
                float b0 = bias[col], b1 = bias[col + 1];
                float2 v01 = make_float2(acc[mi][n][0] + b0, acc[mi][n][1] + b1);
                float2 v23 = make_float2(acc[mi][n][2] + b0, acc[mi][n][3] + b1);
                *(float2*)&outF[(size_t)row0 * ldo + col] = v01;
                *(float2*)&outF[(size_t)(row0 + 8) * ldo + col] = v23;
            }
        }
    }
}

// ---------------- flash attention (double-buffered cp.async) ----------------
#define FPAD 72   // halfs: 144B row stride

__global__ __launch_bounds__(128)
void flash_kernel() {
    __shared__ __align__(16) __half bufK[2][64 * FPAD];
    __shared__ __align__(16) __half bufV[2][64 * FPAD];

    const int tid  = threadIdx.x;
    const int lane = tid & 31;
    const int warp = tid >> 5;
    const int qt = blockIdx.x;
    const int bh = blockIdx.y;
    const int b = bh >> 4, h = bh & 15;

    const size_t base = (size_t)b * HN * QKVC + (size_t)h * HD;

    const uint32_t kb0 = (uint32_t)__cvta_generic_to_shared(&bufK[0][0]);
    const uint32_t kb1 = (uint32_t)__cvta_generic_to_shared(&bufK[1][0]);
    const uint32_t vb0 = (uint32_t)__cvta_generic_to_shared(&bufV[0][0]);
    const uint32_t vb1 = (uint32_t)__cvta_generic_to_shared(&bufV[1][0]);

    // stage Q tile (64 x 64) into bufK[0]
#pragma unroll
    for (int i = 0; i < 4; ++i) {
        int idx = tid + i * 128;
        int r = idx >> 3, c = (idx & 7) * 8;
        *(uint4*)&bufK[0][r * FPAD + c] =
            *(const uint4*)&g_QKV[base + (size_t)(qt * 64 + r) * QKVC + c];
    }
    __syncthreads();

    uint32_t qa[4][4];
    const int a_row = warp * 16 + (lane & 7) + ((lane >> 3) & 1) * 8;
    const int a_col = (lane >> 4) * 8;
#pragma unroll
    for (int kc = 0; kc < 4; ++kc)
        ldm_x4(qa[kc], &bufK[0][a_row * FPAD + a_col + kc * 16]);
    __syncthreads();

    auto issue = [&](int kt, int s) {
        const size_t rowbase = base + (size_t)(kt * 64) * QKVC;
        const uint32_t kb = s ? kb1 : kb0;
        const uint32_t vb = s ? vb1 : vb0;
#pragma unroll
        for (int i = 0; i < 4; ++i) {
            int idx = tid + i * 128;
            int r = idx >> 3, c = idx & 7;
            size_t off = rowbase + (size_t)r * QKVC + c * 8;
            uint32_t so = (uint32_t)(r * FPAD + c * 8) * 2;
            cpasync16(kb + so, &g_QKV[off + 1024]);
            cpasync16(vb + so, &g_QKV[off + 2048]);
        }
        cp_commit();
    };

    float o[8][4];
#pragma unroll
    for (int n = 0; n < 8; ++n)
#pragma unroll
        for (int k = 0; k < 4; ++k) o[n][k] = 0.f;
    float m0 = -1e30f, m1 = -1e30f, l0 = 0.f, l1 = 0.f;

    const int kb_row = (lane >> 4) * 8 + (lane & 7);
    const int kb_col = ((lane >> 3) & 1) * 8;
    const int v_row  = ((lane >> 3) & 1) * 8 + (lane & 7);
    const int v_col  = (lane >> 4) * 8;

    issue(0, 0);

#pragma unroll 1
    for (int kt = 0; kt < 32; ++kt) {
        const int s = kt & 1;
        if (kt + 1 < 32) { issue(kt + 1, s ^ 1); cp_wait<1>(); }
        else             { cp_wait<0>(); }
        __syncthreads();
        const __half* Ks = &bufK[s][0];
        const __half* Vs = &bufV[s][0];

        float sc[8][4];
#pragma unroll
        for (int n = 0; n < 8; ++n)
#pragma unroll
            for (int k = 0; k < 4; ++k) sc[n][k] = 0.f;
#pragma unroll
        for (int kc = 0; kc < 4; ++kc) {
            uint32_t bfr[8][2];
#pragma unroll
            for (int np = 0; np < 4; ++np) {
                uint32_t r[4];
                ldm_x4(r, &Ks[(kb_row + np * 16) * FPAD + kb_col + kc * 16]);
                bfr[2 * np][0] = r[0]; bfr[2 * np][1] = r[1];
                bfr[2 * np + 1][0] = r[2]; bfr[2 * np + 1][1] = r[3];
            }
#pragma unroll
            for (int n = 0; n < 8; ++n)
                mma_f16(sc[n], qa[kc], bfr[n]);
        }
#pragma unroll
        for (int n = 0; n < 8; ++n)
#pragma unroll
            for (int k = 0; k < 4; ++k) sc[n][k] *= 0.125f;

        float tm0 = -1e30f, tm1 = -1e30f;
#pragma unroll
        for (int n = 0; n < 8; ++n) {
            tm0 = fmaxf(tm0, fmaxf(sc[n][0], sc[n][1]));
            tm1 = fmaxf(tm1, fmaxf(sc[n][2], sc[n][3]));
        }
        tm0 = fmaxf(tm0, __shfl_xor_sync(0xffffffffu, tm0, 1));
        tm0 = fmaxf(tm0, __shfl_xor_sync(0xffffffffu, tm0, 2));
        tm1 = fmaxf(tm1, __shfl_xor_sync(0xffffffffu, tm1, 1));
        tm1 = fmaxf(tm1, __shfl_xor_sync(0xffffffffu, tm1, 2));
        float nm0 = fmaxf(m0, tm0), nm1 = fmaxf(m1, tm1);
        float c0 = __expf(m0 - nm0), c1 = __expf(m1 - nm1);
        m0 = nm0; m1 = nm1;

        float rs0 = 0.f, rs1 = 0.f;
#pragma unroll
        for (int n = 0; n < 8; ++n) {
            sc[n][0] = __expf(sc[n][0] - m0); rs0 += sc[n][0];
            sc[n][1] = __expf(sc[n][1] - m0); rs0 += sc[n][1];
            sc[n][2] = __expf(sc[n][2] - m1); rs1 += sc[n][2];
            sc[n][3] = __expf(sc[n][3] - m1); rs1 += sc[n][3];
        }
        rs0 += __shfl_xor_sync(0xffffffffu, rs0, 1);
        rs0 += __shfl_xor_sync(0xffffffffu, rs0, 2);
        rs1 += __shfl_xor_sync(0xffffffffu, rs1, 1);
        rs1 += __shfl_xor_sync(0xffffffffu, rs1, 2);
        l0 = l0 * c0 + rs0;
        l1 = l1 * c1 + rs1;
#pragma unroll
        for (int n = 0; n < 8; ++n) {
            o[n][0] *= c0; o[n][1] *= c0; o[n][2] *= c1; o[n][3] *= c1;
        }

#pragma unroll
        for (int jc = 0; jc < 4; ++jc) {
            uint32_t pa[4];
            pa[0] = h2_as_u32(__floats2half2_rn(sc[2 * jc][0],     sc[2 * jc][1]));
            pa[1] = h2_as_u32(__floats2half2_rn(sc[2 * jc][2],     sc[2 * jc][3]));
            pa[2] = h2_as_u32(__floats2half2_rn(sc[2 * jc + 1][0], sc[2 * jc + 1][1]));
            pa[3] = h2_as_u32(__floats2half2_rn(sc[2 * jc + 1][2], sc[2 * jc + 1][3]));
            uint32_t bv[8][2];
#pragma unroll
            for (int dp = 0; dp < 4; ++dp) {
                uint32_t r[4];
                ldm_x4_t(r, &Vs[(v_row + jc * 16) * FPAD + v_col + dp * 16]);
                bv[2 * dp][0] = r[0]; bv[2 * dp][1] = r[1];
                bv[2 * dp + 1][0] = r[2]; bv[2 * dp + 1][1] = r[3];
            }
#pragma unroll
            for (int dt = 0; dt < 8; ++dt)
                mma_f16(o[dt], pa, bv[dt]);
        }
        __syncthreads();
    }

    // epilogue: divide by l, write O (fp16)
    const float inv0 = 1.0f / l0, inv1 = 1.0f / l1;
    const int g = lane >> 2, tg = lane & 3;
    const int qrow = qt * 64 + warp * 16 + g;
    const size_t obase = ((size_t)b * HN + qrow) * HC + h * HD;
#pragma unroll
    for (int dt = 0; dt < 8; ++dt) {
        int col = dt * 8 + 2 * tg;
        *(__half2*)&g_O[obase + col] =
            __floats2half2_rn(o[dt][0] * inv0, o[dt][1] * inv0);
        *(__half2*)&g_O[obase + (size_t)8 * HC + col] =
            __floats2half2_rn(o[dt][2] * inv1, o[dt][3] * inv1);
    }
}

// ---------------- launch ----------------
extern "C" void kernel_launch(void* const* d_in, const int* in_sizes, int n_in,
                              void* d_out, int out_size) {
    const float* x     = (const float*)d_in[0];
    const float* w_qkv = (const float*)d_in[1];
    const float* w_out = (const float*)d_in[2];
    const float* b_out = (const float*)d_in[3];

    __half *xhi, *wqh, *wql, *woh, *wol, *qkv, *ohi;
    cudaGetSymbolAddress((void**)&xhi, g_Xhi);
    cudaGetSymbolAddress((void**)&wqh, g_Wqkvhi);
    cudaGetSymbolAddress((void**)&wql, g_Wqkvlo);
    cudaGetSymbolAddress((void**)&woh, g_Wouthi);
    cudaGetSymbolAddress((void**)&wol, g_Woutlo);
    cudaGetSymbolAddress((void**)&qkv, g_QKV);
    cudaGetSymbolAddress((void**)&ohi, g_O);

    static int smem_set = 0;
    if (!smem_set) {
        cudaFuncSetAttribute(gemm2_kernel<0>, cudaFuncAttributeMaxDynamicSharedMemorySize, GEMM_SMEM);
        cudaFuncSetAttribute(gemm2_kernel<1>, cudaFuncAttributeMaxDynamicSharedMemorySize, GEMM_SMEM);
        smem_set = 1;
    }

    const int nx = MROWS * HC;
    const int nq = QKVC * HC;
    const int nw = HC * HC;
    convert_hi_kernel<<<nx / 512, 256>>>(x, xhi, nx);
    split_convert_kernel<<<nq / 512, 256>>>(w_qkv, wqh, wql, nq);
    split_convert_kernel<<<nw / 512, 256>>>(w_out, woh, wol, nw);

    // QKV projection: [8192, 3072] fp16
    gemm2_kernel<0><<<dim3(QKVC / BN, MROWS / BM), 256, GEMM_SMEM>>>(
        xhi, wqh, wql, HC, qkv, QKVC, nullptr, nullptr);

    // attention
    flash_kernel<<<dim3(HN / 64, HB * HH), 128>>>();

    // output projection: fp32 + bias
    gemm2_kernel<1><<<dim3(HC / BN, MROWS / BM), 256, GEMM_SMEM>>>(
        ohi, woh, wol, HC, nullptr, HC, (float*)d_out, b_out);
}